// round 17
// baseline (speedup 1.0000x reference)
#include <cuda_runtime.h>
#include <cuda_fp16.h>
#include <cstdint>
#include <math.h>

// Trilinear scatter of B x N points into B x 64^3 grids.
// Scatter: all 8 corners of a point in ONE red.global.add.noftz.v4.f16x2
// (octant layout: 8 parity grids; an 8-half block is one 2x2x2 corner cube).
// Merge: one thread per output quad cell, 27 uint4 loads, compile-time lanes.
// Pipeline: batches processed in chunks; each stage-kernel mixes three CTA
// roles on disjoint chunks (scatter k | merge k-1 | zero k-2) so the memset
// and merge hide under the scatter's atomic wall on a SINGLE stream (graph-
// safe, no stream/event creation). Scratch is left all-zero by each replay.
#define HALF_EXT 32
#define GSIDE    64
#define GRID3    (GSIDE * GSIDE * GSIDE)     // 1<<18
#define CAP_B    32
#define NCHUNK   8

// Batch-major scratch: [batch][pg][64^3] halves (4MB per batch). Statically
// zero-initialized at module load; every replay restores it to zero.
__device__ __align__(16) __half g_oct[(size_t)CAP_B * 8 * GRID3];

__device__ __forceinline__ unsigned pack2(float lo, float hi) {
    __half2 v = __floats2half2_rn(lo, hi);
    return *(const unsigned*)&v;
}
__device__ __forceinline__ void red_v4h2(__half* p, unsigned a, unsigned b,
                                         unsigned c, unsigned d) {
    asm volatile("red.global.add.noftz.v4.f16x2 [%0], {%1,%2,%3,%4};"
                 :: "l"(p), "r"(a), "r"(b), "r"(c), "r"(d) : "memory");
}
__device__ __forceinline__ void red_f32(float* a, float v) {
    asm volatile("red.global.add.f32 [%0], %1;" :: "l"(a), "f"(v) : "memory");
}

// One kernel, three block roles selected by blockIdx.x range.
__global__ void __launch_bounds__(256)
stage_kernel(const float* __restrict__ pt, float* __restrict__ out, int N,
             int sB0, int sNB,   // scatter batches [sB0, sB0+sNB)
             int mB0, int mNB,   // merge batches
             int zB0, int zNB)   // zero batches
{
    const int sBlocksPerB = (N + 255) >> 8;
    const int sBlocks = sNB * sBlocksPerB;
    const int mBlocks = mNB * 128;            // 32768 quads / 256 thr
    int bi = blockIdx.x;

    if (bi < sBlocks) {
        // ---------------- scatter role ----------------
        int b = sB0 + bi / sBlocksPerB;
        int n = (bi % sBlocksPerB) * 256 + threadIdx.x;
        if (n >= N) return;

        const float* p = pt + ((size_t)b * N + n) * 3;
        float x = p[0] * (float)HALF_EXT;
        float y = p[1] * (float)HALF_EXT;
        float z = p[2] * (float)HALF_EXT;

        float m = ((x + y + z) != 0.0f) ? 1.0f : 0.0f;  // ref drops sum==0

        float fx = floorf(x), fy = floorf(y), fz = floorf(z);
        float tx = x - fx, ty = y - fy, tz = z - fz;

        int ix = min(max((int)fx + HALF_EXT, 0), GSIDE - 2);
        int iy = min(max((int)fy + HALF_EXT, 0), GSIDE - 2);
        int iz = min(max((int)fz + HALF_EXT, 0), GSIDE - 2);

        float wx0 = 1.0f - tx, wx1 = tx;
        float wy0 = 1.0f - ty, wy1 = ty;
        float wz0 = (1.0f - tz) * m, wz1 = tz * m;

        int px = ix & 1, py = iy & 1, pz = iz & 1;
        int pg = (px << 2) | (py << 1) | pz;
        int xq = (ix + px) >> 1, yq = (iy + py) >> 1, zq = (iz + pz) >> 1;
        int idx = (((xq * 32 + yq) * 32 + zq) << 3);   // aligned 8-half block

        __half* addr = g_oct + (((size_t)(b * 8 + pg) << 18) + idx);

        unsigned h0 = pack2(wx0 * wy0 * wz0, wx0 * wy0 * wz1);
        unsigned h1 = pack2(wx0 * wy1 * wz0, wx0 * wy1 * wz1);
        unsigned h2 = pack2(wx1 * wy0 * wz0, wx1 * wy0 * wz1);
        unsigned h3 = pack2(wx1 * wy1 * wz0, wx1 * wy1 * wz1);
        red_v4h2(addr, h0, h1, h2, h3);

    } else if (bi < sBlocks + mBlocks) {
        // ---------------- merge role ----------------
        int li = bi - sBlocks;
        int b  = mB0 + (li >> 7);
        int q  = ((li & 127) << 8) + threadIdx.x;      // quad id in [0,32768)
        int xq = q >> 10, yq = (q >> 5) & 31, zq = q & 31;

        float2 acc[2][2];
        acc[0][0] = make_float2(0.f, 0.f); acc[0][1] = make_float2(0.f, 0.f);
        acc[1][0] = make_float2(0.f, 0.f); acc[1][1] = make_float2(0.f, 0.f);

        #pragma unroll
        for (int pg = 0; pg < 8; pg++) {
            const int px = pg >> 2, py = (pg >> 1) & 1, pz = pg & 1;
            const __half* gp = g_oct + ((size_t)(b * 8 + pg) << 18);
            unsigned w[2][2][2][4];
            #pragma unroll
            for (int a = 0; a <= px; a++)
                #pragma unroll
                for (int e = 0; e <= py; e++)
                    #pragma unroll
                    for (int c = 0; c <= pz; c++) {
                        int qx = xq + a, qy = yq + e, qz = zq + c;
                        uint4 v = make_uint4(0u, 0u, 0u, 0u);
                        if (qx < 32 && qy < 32 && qz < 32)
                            v = *(const uint4*)(gp +
                                  (size_t)(((((qx << 5) | qy) << 5) | qz) << 3));
                        w[a][e][c][0] = v.x; w[a][e][c][1] = v.y;
                        w[a][e][c][2] = v.z; w[a][e][c][3] = v.w;
                    }
            #pragma unroll
            for (int xl = 0; xl < 2; xl++)
                #pragma unroll
                for (int yl = 0; yl < 2; yl++) {
                    const int a  = (xl + px) >> 1;
                    const int e  = (yl + py) >> 1;
                    const int wi = (((xl + px) & 1) << 1) | ((yl + py) & 1);
                    unsigned word;
                    if (pz == 0) {
                        word = w[a][e][0][wi];           // halves = (z, z+1)
                    } else {
                        word = (w[a][e][0][wi] >> 16) | (w[a][e][1][wi] << 16);
                    }
                    float2 f = __half22float2(*(const __half2*)&word);
                    acc[xl][yl].x += f.x;
                    acc[xl][yl].y += f.y;
                }
        }

        float* o = out + ((size_t)b << 18)
                       + ((size_t)(xq << 1) << 12) + ((yq << 1) << 6) + (zq << 1);
        *(float2*)(o)             = acc[0][0];
        *(float2*)(o + 64)        = acc[0][1];
        *(float2*)(o + 4096)      = acc[1][0];
        *(float2*)(o + 4096 + 64) = acc[1][1];

    } else {
        // ---------------- zero role ----------------
        // 4MB scratch per batch = 262144 uint4; 256 blocks/batch, each block
        // 1024 uint4 (threads write 4 x uint4 at stride 256).
        int li = bi - sBlocks - mBlocks;               // [0, zNB*256)
        int b  = zB0 + (li >> 8);
        uint4* base = (uint4*)g_oct + ((size_t)b << 18)
                    + ((size_t)(li & 255) << 10) + threadIdx.x;
        const uint4 zz = make_uint4(0u, 0u, 0u, 0u);
        base[0]   = zz;
        base[256] = zz;
        base[512] = zz;
        base[768] = zz;
    }
}

// ---- fp32 fallback (round-1 design) for unexpected shapes ----
__global__ void scatter_f32_kernel(const float* __restrict__ pt,
                                   float* __restrict__ out, int N) {
    int n = blockIdx.x * blockDim.x + threadIdx.x;
    int b = blockIdx.y;
    if (n >= N) return;
    const float* p = pt + ((size_t)b * N + n) * 3;
    float x = p[0] * 32.f, y = p[1] * 32.f, z = p[2] * 32.f;
    float m = ((x + y + z) != 0.0f) ? 1.0f : 0.0f;
    float fx = floorf(x), fy = floorf(y), fz = floorf(z);
    float tx = x - fx, ty = y - fy, tz = z - fz;
    int ix = min(max((int)fx + 32, 0), 62);
    int iy = min(max((int)fy + 32, 0), 62);
    int iz = min(max((int)fz + 32, 0), 62);
    float wx0 = 1.f - tx, wy0 = 1.f - ty;
    float wz0 = (1.f - tz) * m, wz1 = tz * m;
    float* g = out + (size_t)b * GRID3;
    float* r = g + (((size_t)ix * GSIDE + iy) * GSIDE + iz);
    red_f32(r,                       wx0 * wy0 * wz0);
    red_f32(r + 1,                   wx0 * wy0 * wz1);
    red_f32(r + GSIDE,               wx0 * ty  * wz0);
    red_f32(r + GSIDE + 1,           wx0 * ty  * wz1);
    red_f32(r + GSIDE * GSIDE,             tx * wy0 * wz0);
    red_f32(r + GSIDE * GSIDE + 1,         tx * wy0 * wz1);
    red_f32(r + GSIDE * GSIDE + GSIDE,     tx * ty  * wz0);
    red_f32(r + GSIDE * GSIDE + GSIDE + 1, tx * ty  * wz1);
}

extern "C" void kernel_launch(void* const* d_in, const int* in_sizes, int n_in,
                              void* d_out, int out_size) {
    const float* pt  = (const float*)d_in[0];
    float*       out = (float*)d_out;

    int B = out_size / GRID3;
    if (B < 1) B = 1;
    int N = (in_sizes[0] / 3) / B;

    if (B <= CAP_B) {
        int nchunk = (B < NCHUNK) ? B : NCHUNK;
        int per = (B + nchunk - 1) / nchunk;
        nchunk = (B + per - 1) / per;
        int sBlocksPerB = (N + 255) / 256;

        for (int k = 0; k < nchunk + 2; k++) {
            int sB0 = 0, sNB = 0, mB0 = 0, mNB = 0, zB0 = 0, zNB = 0;
            if (k < nchunk) {                     // scatter chunk k
                sB0 = k * per; sNB = (sB0 + per <= B) ? per : (B - sB0);
            }
            if (k >= 1 && k - 1 < nchunk) {       // merge chunk k-1
                mB0 = (k - 1) * per; mNB = (mB0 + per <= B) ? per : (B - mB0);
            }
            if (k >= 2 && k - 2 < nchunk) {       // zero chunk k-2 (for next replay)
                zB0 = (k - 2) * per; zNB = (zB0 + per <= B) ? per : (B - zB0);
            }
            int grid = sNB * sBlocksPerB + mNB * 128 + zNB * 256;
            if (grid > 0)
                stage_kernel<<<grid, 256>>>(pt, out, N,
                                            sB0, sNB, mB0, mNB, zB0, zNB);
        }
    } else {
        cudaMemsetAsync(d_out, 0, (size_t)out_size * sizeof(float));
        dim3 block(256, 1, 1);
        dim3 grid((N + 255) / 256, B, 1);
        scatter_f32_kernel<<<grid, block>>>(pt, out, N);
    }
}